// round 14
// baseline (speedup 1.0000x reference)
#include <cuda_runtime.h>

#define NN    10000
#define NE    320000
#define HID   16
#define NL    7
#define KTOT  10000

// gemm1 tiling: R11 config, grid trimmed to one wave
#define TPB     128           // 4 warps/CTA, each warp independent
#define RPW     128           // rows per warp (4 per thread)
#define KS      16            // k per step; 625 steps total
#define NSPLIT  14            // grid 20x14=280 <= 296 concurrent (2 CTAs/SM) -> 1 wave
#define APITCH  20            // conflict-free LDS.128 pitch

// -------- scratch (no allocations allowed; zero-initialized at module load) ----
__device__ float g_deg_out[NN];
__device__ float g_deg_in[NN];
__device__ float g_norm_src[NN];
__device__ float g_norm_dst[NN];
__device__ float g_h[NN * HID];
__device__ float g_agg1[NN * HID];
__device__ float g_h2[NN * 8];
__device__ float g_agg2[NN * 8];
__device__ int   g_is64;

__device__ __forceinline__ void red_add_v4(float* p, float a, float b, float c, float d) {
    asm volatile("red.global.add.v4.f32 [%0], {%1, %2, %3, %4};"
                 :: "l"(p), "f"(a), "f"(b), "f"(c), "f"(d) : "memory");
}

// -------- degrees (+ inline int64/int32 detection) --------
// deg arrays are zero on entry: static-init on first run, re-zeroed by
// final_kernel at the end of every run (postcondition == precondition).
__global__ void degree_kernel(const int* __restrict__ src, const int* __restrict__ dst) {
    int is64 = ((src[1] | src[3] | src[5] | src[7] |
                 dst[1] | dst[3] | dst[5] | dst[7]) == 0) ? 1 : 0;
    int e = blockIdx.x * blockDim.x + threadIdx.x;
    if (e == 0) g_is64 = is64;
    if (e >= NE) return;
    int s = is64 ? src[2 * e] : src[e];
    int d = is64 ? dst[2 * e] : dst[e];
    atomicAdd(&g_deg_out[s], 1.f);
    atomicAdd(&g_deg_in[d], 1.f);
}

// -------- rsqrt norms + zero g_h / g_agg1 --------
__global__ void norm_kernel() {
    int i = blockIdx.x * blockDim.x + threadIdx.x;
    if (i >= NN) return;
    g_norm_src[i] = rsqrtf(fmaxf(g_deg_out[i], 1.f));
    g_norm_dst[i] = rsqrtf(fmaxf(g_deg_in[i], 1.f));
    float4 z = make_float4(0.f, 0.f, 0.f, 0.f);
    float4* ph = reinterpret_cast<float4*>(&g_h[i * HID]);
    float4* pa = reinterpret_cast<float4*>(&g_agg1[i * HID]);
#pragma unroll
    for (int q = 0; q < 4; q++) { ph[q] = z; pa[q] = z; }
}

// -------- layer1 GEMM: warp-autonomous, 4 rows/thread, cp.async dbl-buffer --------
__global__ __launch_bounds__(TPB, 2) void gemm1_kernel(const float* __restrict__ A,
                                                       const float* __restrict__ W1) {
    __shared__ float As[4][2][RPW * APITCH];   // 4 warps x 2 buf x 2560f = 81920 B
    __shared__ float Ww[4][2][KS * HID];       // 4 warps x 2 buf x 256f  =  8192 B

    const int t    = threadIdx.x;
    const int lane = t & 31;
    const int wid  = t >> 5;
    const int r0   = (blockIdx.x * 4 + wid) * RPW;
    if (r0 >= NN) return;                      // idle warp: safe, no block syncs

    const int by = blockIdx.y;
    const int sb = (by * 625) / NSPLIT;        // balanced step-range [sb, se)
    const int se = ((by + 1) * 625) / NSPLIT;
    const int k0 = sb * KS;
    const int S  = se - sb;                    // 44 or 45

    float (*Aw)[RPW * APITCH] = As[wid];
    float (*Wp)[KS * HID]     = Ww[wid];

    auto prefetch = [&](int s, int b) {
        const int kbase = k0 + s * KS;
        // A tile: 128 rows x 16 k = 512 float4; 16 per lane
#pragma unroll
        for (int p = 0; p < 16; p++) {
            int fi = lane + 32 * p;
            int row = fi >> 2, seg = fi & 3;
            int gr = r0 + row;
            bool ok = gr < NN;
            const void* gp = ok ? (const void*)(A + (size_t)gr * KTOT + kbase + seg * 4)
                                : (const void*)A;
            int n = ok ? 16 : 0;
            unsigned sA = (unsigned)__cvta_generic_to_shared(&Aw[b][row * APITCH + seg * 4]);
            asm volatile("cp.async.cg.shared.global [%0], [%1], 16, %2;"
                         :: "r"(sA), "l"(gp), "r"(n));
        }
        // W tile: 16 x 16 = 64 float4; 2 per lane
#pragma unroll
        for (int p = 0; p < 2; p++) {
            int fi = lane + 32 * p;
            int kw = fi >> 2, u = fi & 3;
            const void* gp = (const void*)(W1 + (size_t)(kbase + kw) * HID + u * 4);
            unsigned sW = (unsigned)__cvta_generic_to_shared(&Wp[b][kw * HID + u * 4]);
            asm volatile("cp.async.cg.shared.global [%0], [%1], 16, 16;"
                         :: "r"(sW), "l"(gp));
        }
        asm volatile("cp.async.commit_group;");
    };

    prefetch(0, 0);

    unsigned long long acc[4][8];
#pragma unroll
    for (int ri = 0; ri < 4; ri++)
#pragma unroll
        for (int j = 0; j < 8; j++) acc[ri][j] = 0ull;

    for (int s = 0; s < S; s++) {
        if (s > 0) __syncwarp();             // all lanes done reading the other buffer
        if (s + 1 < S) {
            prefetch(s + 1, (s + 1) & 1);
            asm volatile("cp.async.wait_group 1;");
        } else {
            asm volatile("cp.async.wait_group 0;");
        }
        __syncwarp();                        // stage s copies complete warp-wide

        const float* as_ = Aw[s & 1];
        const float* wp  = Wp[s & 1];
#pragma unroll
        for (int kq = 0; kq < 4; kq++) {
            float4 a0 = *reinterpret_cast<const float4*>(&as_[(lane     ) * APITCH + kq * 4]);
            float4 a1 = *reinterpret_cast<const float4*>(&as_[(lane + 32) * APITCH + kq * 4]);
            float4 a2 = *reinterpret_cast<const float4*>(&as_[(lane + 64) * APITCH + kq * 4]);
            float4 a3 = *reinterpret_cast<const float4*>(&as_[(lane + 96) * APITCH + kq * 4]);
#pragma unroll
            for (int kk = 0; kk < 4; kk++) {
                const ulonglong2* wr =
                    reinterpret_cast<const ulonglong2*>(wp + (kq * 4 + kk) * HID);
                ulonglong2 wa = wr[0], wb = wr[1], wc = wr[2], wd = wr[3];
                unsigned long long w[8] = {wa.x, wa.y, wb.x, wb.y, wc.x, wc.y, wd.x, wd.y};
                float e0 = kk == 0 ? a0.x : kk == 1 ? a0.y : kk == 2 ? a0.z : a0.w;
                float e1 = kk == 0 ? a1.x : kk == 1 ? a1.y : kk == 2 ? a1.z : a1.w;
                float e2 = kk == 0 ? a2.x : kk == 1 ? a2.y : kk == 2 ? a2.z : a2.w;
                float e3 = kk == 0 ? a3.x : kk == 1 ? a3.y : kk == 2 ? a3.z : a3.w;
                unsigned long long d0, d1, d2, d3;
                asm("mov.b64 %0, {%1, %1};" : "=l"(d0) : "r"(__float_as_uint(e0)));
                asm("mov.b64 %0, {%1, %1};" : "=l"(d1) : "r"(__float_as_uint(e1)));
                asm("mov.b64 %0, {%1, %1};" : "=l"(d2) : "r"(__float_as_uint(e2)));
                asm("mov.b64 %0, {%1, %1};" : "=l"(d3) : "r"(__float_as_uint(e3)));
#pragma unroll
                for (int j = 0; j < 8; j++) {
                    asm("fma.rn.f32x2 %0, %1, %2, %0;" : "+l"(acc[0][j]) : "l"(d0), "l"(w[j]));
                    asm("fma.rn.f32x2 %0, %1, %2, %0;" : "+l"(acc[1][j]) : "l"(d1), "l"(w[j]));
                    asm("fma.rn.f32x2 %0, %1, %2, %0;" : "+l"(acc[2][j]) : "l"(d2), "l"(w[j]));
                    asm("fma.rn.f32x2 %0, %1, %2, %0;" : "+l"(acc[3][j]) : "l"(d3), "l"(w[j]));
                }
            }
        }
    }

    // epilogue: scale by norm_src, vector-reduce into g_h
#pragma unroll
    for (int ri = 0; ri < 4; ri++) {
        int row = r0 + lane + 32 * ri;
        if (row < NN) {
            float ns = g_norm_src[row];
            float v[16];
#pragma unroll
            for (int j = 0; j < 8; j++) {
                float2 p = *reinterpret_cast<float2*>(&acc[ri][j]);
                v[2 * j] = p.x * ns;
                v[2 * j + 1] = p.y * ns;
            }
            red_add_v4(&g_h[row * HID + 0],  v[0],  v[1],  v[2],  v[3]);
            red_add_v4(&g_h[row * HID + 4],  v[4],  v[5],  v[6],  v[7]);
            red_add_v4(&g_h[row * HID + 8],  v[8],  v[9],  v[10], v[11]);
            red_add_v4(&g_h[row * HID + 12], v[12], v[13], v[14], v[15]);
        }
    }
}

// -------- edge scatter 1: one thread per edge, 4x red.v4 --------
__global__ void scatter1_kernel(const int* __restrict__ src, const int* __restrict__ dst) {
    int e = blockIdx.x * blockDim.x + threadIdx.x;
    if (e >= NE) return;
    int is64 = g_is64;
    int s = is64 ? src[2 * e] : src[e];
    int d = is64 ? dst[2 * e] : dst[e];
    const float4* hp = reinterpret_cast<const float4*>(&g_h[s * HID]);
    float4 v0 = hp[0], v1 = hp[1], v2 = hp[2], v3 = hp[3];
    float* o = &g_agg1[d * HID];
    red_add_v4(o + 0,  v0.x, v0.y, v0.z, v0.w);
    red_add_v4(o + 4,  v1.x, v1.y, v1.z, v1.w);
    red_add_v4(o + 8,  v2.x, v2.y, v2.z, v2.w);
    red_add_v4(o + 12, v3.x, v3.y, v3.z, v3.w);
}

// -------- relu + norm + layer2 GEMM (16x7), also zeroes agg2 --------
__global__ void act_gemm2_kernel(const float* __restrict__ b1, const float* __restrict__ W2) {
    __shared__ float W2s[HID * NL];
    __shared__ float b1s[HID];
    int t = threadIdx.x;
    if (t < HID * NL) W2s[t] = W2[t];
    if (t < HID) b1s[t] = b1[t];
    __syncthreads();
    int i = blockIdx.x * blockDim.x + t;
    if (i >= NN) return;
    *reinterpret_cast<float4*>(&g_agg2[i * 8])     = make_float4(0.f, 0.f, 0.f, 0.f);
    *reinterpret_cast<float4*>(&g_agg2[i * 8 + 4]) = make_float4(0.f, 0.f, 0.f, 0.f);

    float nd = g_norm_dst[i], ns = g_norm_src[i];
    float o[8];
#pragma unroll
    for (int l = 0; l < 8; l++) o[l] = 0.f;
    const float4* ag = (const float4*)(g_agg1 + i * HID);
#pragma unroll
    for (int qq = 0; qq < 4; qq++) {
        float4 v = ag[qq];
        float hv[4] = {v.x, v.y, v.z, v.w};
#pragma unroll
        for (int u = 0; u < 4; u++) {
            int j = qq * 4 + u;
            float h1 = fmaxf(hv[u] * nd + b1s[j], 0.f) * ns;
#pragma unroll
            for (int l = 0; l < NL; l++) o[l] += h1 * W2s[j * NL + l];
        }
    }
    *reinterpret_cast<float4*>(&g_h2[i * 8])     = make_float4(o[0], o[1], o[2], o[3]);
    *reinterpret_cast<float4*>(&g_h2[i * 8 + 4]) = make_float4(o[4], o[5], o[6], 0.f);
}

// -------- edge scatter 2: one thread per edge, 2x red.v4 --------
__global__ void scatter2_kernel(const int* __restrict__ src, const int* __restrict__ dst) {
    int e = blockIdx.x * blockDim.x + threadIdx.x;
    if (e >= NE) return;
    int is64 = g_is64;
    int s = is64 ? src[2 * e] : src[e];
    int d = is64 ? dst[2 * e] : dst[e];
    const float4* hp = reinterpret_cast<const float4*>(&g_h2[s * 8]);
    float4 v0 = hp[0], v1 = hp[1];
    float* o = &g_agg2[d * 8];
    red_add_v4(o + 0, v0.x, v0.y, v0.z, v0.w);
    red_add_v4(o + 4, v1.x, v1.y, v1.z, v1.w);
}

// -------- epilogue: out = agg2 * norm_dst + b2 ; re-zero degree arrays --------
__global__ void final_kernel(const float* __restrict__ b2, float* __restrict__ out) {
    int idx = blockIdx.x * blockDim.x + threadIdx.x;
    if (idx < NN) { g_deg_out[idx] = 0.f; g_deg_in[idx] = 0.f; }   // for next run
    if (idx >= NN * NL) return;
    int i = idx / NL, l = idx - i * NL;
    out[idx] = g_agg2[i * 8 + l] * g_norm_dst[i] + __ldg(&b2[l]);
}

extern "C" void kernel_launch(void* const* d_in, const int* in_sizes, int n_in,
                              void* d_out, int out_size) {
    const float* features = (const float*)d_in[0];
    const int*   src      = (const int*)d_in[1];   // int32 or int64 (runtime-detected)
    const int*   dst      = (const int*)d_in[2];
    const float* W1       = (const float*)d_in[3];
    const float* b1       = (const float*)d_in[4];
    const float* W2       = (const float*)d_in[5];
    const float* b2       = (const float*)d_in[6];
    float* out = (float*)d_out;

    degree_kernel<<<(NE + 255) / 256, 256>>>(src, dst);
    norm_kernel<<<(NN + 255) / 256, 256>>>();
    gemm1_kernel<<<dim3((NN + 4 * RPW - 1) / (4 * RPW), NSPLIT), TPB>>>(features, W1);
    scatter1_kernel<<<(NE + 255) / 256, 256>>>(src, dst);
    act_gemm2_kernel<<<(NN + 255) / 256, 256>>>(b1, W2);
    scatter2_kernel<<<(NE + 255) / 256, 256>>>(src, dst);
    final_kernel<<<(NN * NL + 255) / 256, 256>>>(b2, out);
}

// round 15
// speedup vs baseline: 1.1010x; 1.1010x over previous
#include <cuda_runtime.h>

#define NN    10000
#define NE    320000
#define HID   16
#define NL    7
#define KTOT  10000

// gemm1 tiling: warp-autonomous, 8 rows/thread, 1 CTA/SM
#define TPB     128           // 4 warps/CTA, each warp independent
#define RPW     256           // rows per warp (8 per thread)
#define KS      16            // k per step; 625 steps total
#define NSPLIT  15            // grid 10x15=150 ~= 148 SMs (1 CTA/SM) -> 1 wave
#define APITCH  20            // conflict-free LDS.128 pitch

// -------- scratch (no allocations allowed) --------
__device__ float g_deg_out[NN];
__device__ float g_deg_in[NN];
__device__ float g_norm_src[NN];
__device__ float g_norm_dst[NN];
__device__ float g_h[NN * HID];
__device__ float g_agg1[NN * HID];
__device__ float g_h2[NN * 8];
__device__ float g_agg2[NN * 8];
__device__ int   g_is64;

__device__ __forceinline__ void red_add_v4(float* p, float a, float b, float c, float d) {
    asm volatile("red.global.add.v4.f32 [%0], {%1, %2, %3, %4};"
                 :: "l"(p), "f"(a), "f"(b), "f"(c), "f"(d) : "memory");
}

// -------- zero degree accumulators --------
__global__ void zero_kernel() {
    int i = blockIdx.x * blockDim.x + threadIdx.x;
    if (i < NN) { g_deg_out[i] = 0.f; g_deg_in[i] = 0.f; }
}

// -------- degrees (+ inline int64/int32 detection) --------
__global__ void degree_kernel(const int* __restrict__ src, const int* __restrict__ dst) {
    int is64 = ((src[1] | src[3] | src[5] | src[7] |
                 dst[1] | dst[3] | dst[5] | dst[7]) == 0) ? 1 : 0;
    int e = blockIdx.x * blockDim.x + threadIdx.x;
    if (e == 0) g_is64 = is64;
    if (e >= NE) return;
    int s = is64 ? src[2 * e] : src[e];
    int d = is64 ? dst[2 * e] : dst[e];
    atomicAdd(&g_deg_out[s], 1.f);
    atomicAdd(&g_deg_in[d], 1.f);
}

// -------- rsqrt norms + zero g_h / g_agg1 --------
__global__ void norm_kernel() {
    int i = blockIdx.x * blockDim.x + threadIdx.x;
    if (i >= NN) return;
    g_norm_src[i] = rsqrtf(fmaxf(g_deg_out[i], 1.f));
    g_norm_dst[i] = rsqrtf(fmaxf(g_deg_in[i], 1.f));
    float4 z = make_float4(0.f, 0.f, 0.f, 0.f);
    float4* ph = reinterpret_cast<float4*>(&g_h[i * HID]);
    float4* pa = reinterpret_cast<float4*>(&g_agg1[i * HID]);
#pragma unroll
    for (int q = 0; q < 4; q++) { ph[q] = z; pa[q] = z; }
}

// -------- layer1 GEMM: warp-autonomous, 8 rows/thread, cp.async dbl-buffer --------
__global__ __launch_bounds__(TPB, 1) void gemm1_kernel(const float* __restrict__ A,
                                                       const float* __restrict__ W1) {
    __shared__ float As[4][2][RPW * APITCH];   // 4 warps x 2 buf x 5120f = 163840 B
    __shared__ float Ww[4][2][KS * HID];       // 4 warps x 2 buf x 256f  =   8192 B

    const int t    = threadIdx.x;
    const int lane = t & 31;
    const int wid  = t >> 5;
    const int r0   = (blockIdx.x * 4 + wid) * RPW;
    if (r0 >= NN) return;                      // idle warp: safe, no block syncs

    const int by = blockIdx.y;
    const int sb = (by * 625) / NSPLIT;        // balanced step-range [sb, se)
    const int se = ((by + 1) * 625) / NSPLIT;
    const int k0 = sb * KS;
    const int S  = se - sb;                    // 41 or 42

    float (*Aw)[RPW * APITCH] = As[wid];
    float (*Wp)[KS * HID]     = Ww[wid];

    auto prefetch = [&](int s, int b) {
        const int kbase = k0 + s * KS;
        // A tile: 256 rows x 16 k = 1024 float4; 32 per lane
#pragma unroll
        for (int p = 0; p < 32; p++) {
            int fi = lane + 32 * p;
            int row = fi >> 2, seg = fi & 3;
            int gr = r0 + row;
            bool ok = gr < NN;
            const void* gp = ok ? (const void*)(A + (size_t)gr * KTOT + kbase + seg * 4)
                                : (const void*)A;
            int n = ok ? 16 : 0;
            unsigned sA = (unsigned)__cvta_generic_to_shared(&Aw[b][row * APITCH + seg * 4]);
            asm volatile("cp.async.cg.shared.global [%0], [%1], 16, %2;"
                         :: "r"(sA), "l"(gp), "r"(n));
        }
        // W tile: 16 x 16 = 64 float4; 2 per lane
#pragma unroll
        for (int p = 0; p < 2; p++) {
            int fi = lane + 32 * p;
            int kw = fi >> 2, u = fi & 3;
            const void* gp = (const void*)(W1 + (size_t)(kbase + kw) * HID + u * 4);
            unsigned sW = (unsigned)__cvta_generic_to_shared(&Wp[b][kw * HID + u * 4]);
            asm volatile("cp.async.cg.shared.global [%0], [%1], 16, 16;"
                         :: "r"(sW), "l"(gp));
        }
        asm volatile("cp.async.commit_group;");
    };

    prefetch(0, 0);

    unsigned long long acc[8][8];
#pragma unroll
    for (int ri = 0; ri < 8; ri++)
#pragma unroll
        for (int j = 0; j < 8; j++) acc[ri][j] = 0ull;

    for (int s = 0; s < S; s++) {
        if (s > 0) __syncwarp();             // all lanes done reading the other buffer
        if (s + 1 < S) {
            prefetch(s + 1, (s + 1) & 1);
            asm volatile("cp.async.wait_group 1;");
        } else {
            asm volatile("cp.async.wait_group 0;");
        }
        __syncwarp();                        // stage s copies complete warp-wide

        const float* as_ = Aw[s & 1];
        const float* wp  = Wp[s & 1];
#pragma unroll
        for (int kq = 0; kq < 4; kq++) {
            float4 av[8];
#pragma unroll
            for (int ri = 0; ri < 8; ri++)
                av[ri] = *reinterpret_cast<const float4*>(
                    &as_[(lane + 32 * ri) * APITCH + kq * 4]);
#pragma unroll
            for (int kk = 0; kk < 4; kk++) {
                const ulonglong2* wr =
                    reinterpret_cast<const ulonglong2*>(wp + (kq * 4 + kk) * HID);
                ulonglong2 wa = wr[0], wb = wr[1], wc = wr[2], wd = wr[3];
                unsigned long long w[8] = {wa.x, wa.y, wb.x, wb.y, wc.x, wc.y, wd.x, wd.y};
#pragma unroll
                for (int ri = 0; ri < 8; ri++) {
                    float e = kk == 0 ? av[ri].x : kk == 1 ? av[ri].y
                            : kk == 2 ? av[ri].z : av[ri].w;
                    unsigned long long d;
                    asm("mov.b64 %0, {%1, %1};" : "=l"(d) : "r"(__float_as_uint(e)));
#pragma unroll
                    for (int j = 0; j < 8; j++) {
                        asm("fma.rn.f32x2 %0, %1, %2, %0;"
                            : "+l"(acc[ri][j]) : "l"(d), "l"(w[j]));
                    }
                }
            }
        }
    }

    // epilogue: scale by norm_src, vector-reduce into g_h
#pragma unroll
    for (int ri = 0; ri < 8; ri++) {
        int row = r0 + lane + 32 * ri;
        if (row < NN) {
            float ns = g_norm_src[row];
            float v[16];
#pragma unroll
            for (int j = 0; j < 8; j++) {
                float2 p = *reinterpret_cast<float2*>(&acc[ri][j]);
                v[2 * j] = p.x * ns;
                v[2 * j + 1] = p.y * ns;
            }
            red_add_v4(&g_h[row * HID + 0],  v[0],  v[1],  v[2],  v[3]);
            red_add_v4(&g_h[row * HID + 4],  v[4],  v[5],  v[6],  v[7]);
            red_add_v4(&g_h[row * HID + 8],  v[8],  v[9],  v[10], v[11]);
            red_add_v4(&g_h[row * HID + 12], v[12], v[13], v[14], v[15]);
        }
    }
}

// -------- edge scatter 1: agg1[dst] += h[src], one red.v4 per (edge, quad) --------
__global__ void scatter1_kernel(const int* __restrict__ src, const int* __restrict__ dst) {
    int idx = blockIdx.x * blockDim.x + threadIdx.x;
    if (idx >= NE * 4) return;
    int e = idx >> 2, q = idx & 3;
    int is64 = g_is64;
    int s = is64 ? src[2 * e] : src[e];
    int d = is64 ? dst[2 * e] : dst[e];
    float4 v = *reinterpret_cast<const float4*>(&g_h[s * HID + q * 4]);
    red_add_v4(&g_agg1[d * HID + q * 4], v.x, v.y, v.z, v.w);
}

// -------- relu + norm + layer2 GEMM (16x7), also zeroes agg2 --------
__global__ void act_gemm2_kernel(const float* __restrict__ b1, const float* __restrict__ W2) {
    __shared__ float W2s[HID * NL];
    __shared__ float b1s[HID];
    int t = threadIdx.x;
    if (t < HID * NL) W2s[t] = W2[t];
    if (t < HID) b1s[t] = b1[t];
    __syncthreads();
    int i = blockIdx.x * blockDim.x + t;
    if (i >= NN) return;
    *reinterpret_cast<float4*>(&g_agg2[i * 8])     = make_float4(0.f, 0.f, 0.f, 0.f);
    *reinterpret_cast<float4*>(&g_agg2[i * 8 + 4]) = make_float4(0.f, 0.f, 0.f, 0.f);

    float nd = g_norm_dst[i], ns = g_norm_src[i];
    float o[8];
#pragma unroll
    for (int l = 0; l < 8; l++) o[l] = 0.f;
    const float4* ag = (const float4*)(g_agg1 + i * HID);
#pragma unroll
    for (int qq = 0; qq < 4; qq++) {
        float4 v = ag[qq];
        float hv[4] = {v.x, v.y, v.z, v.w};
#pragma unroll
        for (int u = 0; u < 4; u++) {
            int j = qq * 4 + u;
            float h1 = fmaxf(hv[u] * nd + b1s[j], 0.f) * ns;
#pragma unroll
            for (int l = 0; l < NL; l++) o[l] += h1 * W2s[j * NL + l];
        }
    }
    *reinterpret_cast<float4*>(&g_h2[i * 8])     = make_float4(o[0], o[1], o[2], o[3]);
    *reinterpret_cast<float4*>(&g_h2[i * 8 + 4]) = make_float4(o[4], o[5], o[6], 0.f);
}

// -------- edge scatter 2: one red.v4 per (edge, half) --------
__global__ void scatter2_kernel(const int* __restrict__ src, const int* __restrict__ dst) {
    int idx = blockIdx.x * blockDim.x + threadIdx.x;
    if (idx >= NE * 2) return;
    int e = idx >> 1, q = idx & 1;
    int is64 = g_is64;
    int s = is64 ? src[2 * e] : src[e];
    int d = is64 ? dst[2 * e] : dst[e];
    float4 v = *reinterpret_cast<const float4*>(&g_h2[s * 8 + q * 4]);
    red_add_v4(&g_agg2[d * 8 + q * 4], v.x, v.y, v.z, v.w);
}

// -------- epilogue: out = agg2 * norm_dst + b2 --------
__global__ void final_kernel(const float* __restrict__ b2, float* __restrict__ out) {
    int idx = blockIdx.x * blockDim.x + threadIdx.x;
    if (idx >= NN * NL) return;
    int i = idx / NL, l = idx - i * NL;
    out[idx] = g_agg2[i * 8 + l] * g_norm_dst[i] + __ldg(&b2[l]);
}

extern "C" void kernel_launch(void* const* d_in, const int* in_sizes, int n_in,
                              void* d_out, int out_size) {
    const float* features = (const float*)d_in[0];
    const int*   src      = (const int*)d_in[1];   // int32 or int64 (runtime-detected)
    const int*   dst      = (const int*)d_in[2];
    const float* W1       = (const float*)d_in[3];
    const float* b1       = (const float*)d_in[4];
    const float* W2       = (const float*)d_in[5];
    const float* b2       = (const float*)d_in[6];
    float* out = (float*)d_out;

    zero_kernel<<<(NN + 255) / 256, 256>>>();
    degree_kernel<<<(NE + 255) / 256, 256>>>(src, dst);
    norm_kernel<<<(NN + 255) / 256, 256>>>();
    gemm1_kernel<<<dim3((NN + 4 * RPW - 1) / (4 * RPW), NSPLIT), TPB>>>(features, W1);
    scatter1_kernel<<<(NE * 4 + 255) / 256, 256>>>(src, dst);
    act_gemm2_kernel<<<(NN + 255) / 256, 256>>>(b1, W2);
    scatter2_kernel<<<(NE * 2 + 255) / 256, 256>>>(src, dst);
    final_kernel<<<(NN * NL + 255) / 256, 256>>>(b2, out);
}